// round 5
// baseline (speedup 1.0000x reference)
#include <cuda_runtime.h>
#include <cstdint>
#include <cstddef>

#define TSTEPS 16384
#define BATCH  32
#define HID    96
#define GATES  384
#define NTH    416   // 12 compute warps + 1 aux (output) warp
#define SMEM_BYTES ((TSTEPS + HID + GATES) * sizeof(float))

// sigmoid / tanh via hardware EX2+RCP (MUFU): ~2 ulp, negligible vs 1e-3 tol.
__device__ __forceinline__ float sigm(float x) {
    return __fdividef(1.0f, 1.0f + __expf(-x));
}
__device__ __forceinline__ float tanh_acc(float x) {
    float ax = fabsf(x);
    float e  = __expf(-2.0f * ax);
    float t  = __fdividef(1.0f - e, 1.0f + e);
    return copysignf(t, x);
}

__global__ void __launch_bounds__(NTH, 1)
lstm_persist(const float* __restrict__ x,
             const float* __restrict__ w_ih,
             const float* __restrict__ w_hh,
             const float* __restrict__ b_ih,
             const float* __restrict__ b_hh,
             const float* __restrict__ fc_w,
             const float* __restrict__ fc_b,
             float* __restrict__ out)
{
    extern __shared__ float smem[];
    float* xs   = smem;             // [TSTEPS]  x column for this batch element
    float* h_sh = smem + TSTEPS;    // [HID]     hidden state (16B-aligned: 64KB offset)
    float* act  = h_sh + HID;       // [GATES]   activated gate values

    const int tid = threadIdx.x;
    const int b   = blockIdx.x;     // one CTA per batch element

    // Stage all of x[:, b] into shared (64KB, one-time ~2MB total traffic).
    for (int t = tid; t < TSTEPS; t += NTH)
        xs[t] = x[(size_t)t * BATCH + b];

    // Per-thread persistent state.
    unsigned long long w2[48];      // W_hh row j, packed as 48 f32x2
    float wih = 0.f, bias = 0.f, c = 0.f;
    float fw0 = 0.f, fw1 = 0.f, fw2 = 0.f, fcb = 0.f;

    if (tid < GATES) {
        // thread j owns gate row j of W_hh (rows: [0,96)=i [96,192)=f [192,288)=g [288,384)=o)
        const unsigned long long* wrow =
            reinterpret_cast<const unsigned long long*>(w_hh + tid * HID);
        #pragma unroll
        for (int k = 0; k < 48; ++k) w2[k] = wrow[k];
        wih  = __ldg(w_ih + tid);
        bias = __ldg(b_ih + tid) + __ldg(b_hh + tid);
    } else {
        const int l = tid - GATES;  // aux warp: fc weights, 3 per lane
        fw0 = fc_w[l]; fw1 = fc_w[l + 32]; fw2 = fc_w[l + 64];
        fcb = fc_b[0];
    }
    if (tid < HID) h_sh[tid] = 0.f;   // h0 = 0, c0 = 0 (c in regs)
    __syncthreads();

    uint32_t h_addr;
    asm("{ .reg .u64 ta; cvta.to.shared.u64 ta, %1; cvt.u32.u64 %0, ta; }"
        : "=r"(h_addr) : "l"(h_sh));

    const bool tanh_gate = (tid >= 2 * HID) && (tid < 3 * HID);  // warp-uniform (96 = 3 warps/gate)

    #pragma unroll 1
    for (int t = 0; t < TSTEPS; ++t) {
        // ---- phase 1: gate matvec (compute warps) | output t-1 (aux warp) ----
        if (tid < GATES) {
            // dot(W_hh[row j], h_{t-1}) via packed fp32x2 FMA (SASS FFMA2).
            unsigned long long acc0 = 0ull, acc1 = 0ull;   // (0.0f,0.0f) bit pattern
            #pragma unroll
            for (int k = 0; k < 24; ++k) {
                unsigned long long ha, hb;
                asm volatile("ld.shared.v2.u64 {%0,%1}, [%2];"   // 16B broadcast load of h
                             : "=l"(ha), "=l"(hb)
                             : "r"(h_addr + 16u * k));
                asm("fma.rn.f32x2 %0, %1, %2, %0;"
                    : "+l"(acc0) : "l"(w2[2 * k]),     "l"(ha));
                asm("fma.rn.f32x2 %0, %1, %2, %0;"
                    : "+l"(acc1) : "l"(w2[2 * k + 1]), "l"(hb));
            }
            unsigned lo0, hi0, lo1, hi1;
            asm("mov.b64 {%0,%1}, %2;" : "=r"(lo0), "=r"(hi0) : "l"(acc0));
            asm("mov.b64 {%0,%1}, %2;" : "=r"(lo1), "=r"(hi1) : "l"(acc1));
            float dot = (__uint_as_float(lo0) + __uint_as_float(hi0))
                      + (__uint_as_float(lo1) + __uint_as_float(hi1));
            // gates_x folded in on the fly: x_t * w_ih[j] + (b_ih[j] + b_hh[j])
            float g = dot + fmaf(xs[t], wih, bias);
            act[tid] = tanh_gate ? tanh_acc(g) : sigm(g);
        } else if (t > 0) {
            // aux warp: out[t-1] = fc_w . h_{t-1} + fc_b + x[t-1]  (h_sh still holds h_{t-1})
            const int l = tid - GATES;
            float p = fw0 * h_sh[l] + fw1 * h_sh[l + 32] + fw2 * h_sh[l + 64];
            #pragma unroll
            for (int off = 16; off > 0; off >>= 1)
                p += __shfl_xor_sync(0xffffffffu, p, off);
            if (l == 0)
                out[(size_t)(t - 1) * BATCH + b] = p + fcb + xs[t - 1];
        }
        __syncthreads();   // act visible; everyone done reading h_sh

        // ---- phase 2: cell/hidden update (threads 0..95) ----
        if (tid < HID) {
            const float gi = act[tid];             // sigmoid(i)
            const float gf = act[tid + HID];       // sigmoid(f)
            const float gg = act[tid + 2 * HID];   // tanh(g)
            const float go = act[tid + 3 * HID];   // sigmoid(o)
            c = fmaf(gf, c, gi * gg);
            h_sh[tid] = go * tanh_acc(c);
        }
        __syncthreads();   // h_t published for next step
    }

    // Final output for t = TSTEPS-1 (h_sh holds h_{T-1} after last barrier).
    if (tid >= GATES) {
        const int l = tid - GATES;
        float p = fw0 * h_sh[l] + fw1 * h_sh[l + 32] + fw2 * h_sh[l + 64];
        #pragma unroll
        for (int off = 16; off > 0; off >>= 1)
            p += __shfl_xor_sync(0xffffffffu, p, off);
        if (l == 0)
            out[(size_t)(TSTEPS - 1) * BATCH + b] = p + fcb + xs[TSTEPS - 1];
    }
}

extern "C" void kernel_launch(void* const* d_in, const int* in_sizes, int n_in,
                              void* d_out, int out_size)
{
    const float* x    = (const float*)d_in[0];
    const float* w_ih = (const float*)d_in[1];
    const float* w_hh = (const float*)d_in[2];
    const float* b_ih = (const float*)d_in[3];
    const float* b_hh = (const float*)d_in[4];
    const float* fc_w = (const float*)d_in[5];
    const float* fc_b = (const float*)d_in[6];
    float* out = (float*)d_out;

    // >48KB dynamic smem needs opt-in; idempotent, non-stream API (capture-safe).
    cudaFuncSetAttribute(lstm_persist,
                         cudaFuncAttributeMaxDynamicSharedMemorySize,
                         (int)SMEM_BYTES);
    lstm_persist<<<BATCH, NTH, SMEM_BYTES>>>(x, w_ih, w_hh, b_ih, b_hh,
                                             fc_w, fc_b, out);
}

// round 6
// speedup vs baseline: 1.0342x; 1.0342x over previous
#include <cuda_runtime.h>
#include <cstdint>
#include <cstddef>

#define TSTEPS 16384
#define BATCH  32
#define HID    96
#define GATES  384
#define NTH    416   // 12 compute warps (384 thr) + 1 aux output warp
#define SMEM_FLOATS (TSTEPS + 2 * HID + 8)
#define SMEM_BYTES  (SMEM_FLOATS * sizeof(float))

__device__ __forceinline__ float tanh_fast(float x) {
    float y;
    asm("tanh.approx.f32 %0, %1;" : "=f"(y) : "f"(x));   // MUFU.TANH, lat~16
    return y;
}

__global__ void __launch_bounds__(NTH, 1)
lstm_persist(const float* __restrict__ x,
             const float* __restrict__ w_ih,
             const float* __restrict__ w_hh,
             const float* __restrict__ b_ih,
             const float* __restrict__ b_hh,
             const float* __restrict__ fc_w,
             const float* __restrict__ fc_b,
             float* __restrict__ out)
{
    extern __shared__ float smem[];
    float* xs = smem;                    // [TSTEPS] x column for this batch elem
    float* hb = smem + TSTEPS;           // [2][HID] double-buffered hidden state

    const int tid = threadIdx.x;
    const int b   = blockIdx.x;          // one CTA / batch element / SM

    // Stage x[:, b] into shared (one-time; L2-amortized across CTAs).
    for (int t = tid; t < TSTEPS; t += NTH)
        xs[t] = x[(size_t)t * BATCH + b];

    // ---- per-thread persistent state ----
    unsigned long long w2[48];           // W_hh row as 48 packed f32x2
    float wih = 0.f, bias = 0.f, c = 0.f;
    float act_a = 0.5f, act_s = 0.5f, act_b = 0.5f;   // sigmoid: 0.5*tanh(0.5x)+0.5
    float fw0 = 0.f, fw1 = 0.f, fw2 = 0.f, fcb = 0.f;
    int   u = 0;

    if (tid < GATES) {
        // quad-interleaved: unit u = tid>>2, gate q = tid&3 (0=i,1=f,2=g,3=o)
        u = tid >> 2;
        const int q   = tid & 3;
        const int row = q * HID + u;     // row in W_hh / w_ih / biases
        const unsigned long long* wrow =
            reinterpret_cast<const unsigned long long*>(w_hh + row * HID);
        #pragma unroll
        for (int k = 0; k < 48; ++k) w2[k] = wrow[k];
        wih  = __ldg(w_ih + row);
        bias = __ldg(b_ih + row) + __ldg(b_hh + row);
        if (q == 2) { act_a = 1.f; act_s = 1.f; act_b = 0.f; }  // g-gate: plain tanh
    } else {
        const int l = tid - GATES;       // aux warp: fc weights, 3 per lane
        fw0 = fc_w[l]; fw1 = fc_w[l + 32]; fw2 = fc_w[l + 64];
        fcb = fc_b[0];
    }
    if (tid < HID) hb[tid] = 0.f;        // h0 = 0 (read buffer for t=0); c0=0 in regs
    __syncthreads();

    float* h_rd = hb;                    // reads h_{t-1}
    float* h_wr = hb + HID;              // writes h_t

    #pragma unroll 1
    for (int t = 0; t < TSTEPS; ++t) {
        if (tid < GATES) {
            // ---- matvec: dot(W_hh[row], h_{t-1}) via packed FFMA2, 4 chains ----
            const ulonglong2* hv = reinterpret_cast<const ulonglong2*>(h_rd);
            unsigned long long a0 = 0ull, a1 = 0ull, a2 = 0ull, a3 = 0ull;
            #pragma unroll
            for (int k = 0; k < 12; ++k) {
                ulonglong2 p = hv[2 * k];
                ulonglong2 r = hv[2 * k + 1];
                asm("fma.rn.f32x2 %0, %1, %2, %0;" : "+l"(a0) : "l"(w2[4*k+0]), "l"(p.x));
                asm("fma.rn.f32x2 %0, %1, %2, %0;" : "+l"(a1) : "l"(w2[4*k+1]), "l"(p.y));
                asm("fma.rn.f32x2 %0, %1, %2, %0;" : "+l"(a2) : "l"(w2[4*k+2]), "l"(r.x));
                asm("fma.rn.f32x2 %0, %1, %2, %0;" : "+l"(a3) : "l"(w2[4*k+3]), "l"(r.y));
            }
            asm("add.rn.f32x2 %0, %0, %1;" : "+l"(a0) : "l"(a1));
            asm("add.rn.f32x2 %0, %0, %1;" : "+l"(a2) : "l"(a3));
            asm("add.rn.f32x2 %0, %0, %1;" : "+l"(a0) : "l"(a2));
            unsigned lo, hi;
            asm("mov.b64 {%0,%1}, %2;" : "=r"(lo), "=r"(hi) : "l"(a0));
            float dot = __uint_as_float(lo) + __uint_as_float(hi);

            // g = dot + x_t*w_ih + (b_ih+b_hh); uniform activation via MUFU.TANH
            float g   = dot + fmaf(xs[t], wih, bias);
            float act = fmaf(tanh_fast(g * act_a), act_s, act_b);

            // ---- cell update via quad shuffles (no smem, no extra barrier) ----
            const unsigned m = 0xffffffffu;
            float gi = __shfl_sync(m, act, 0, 4);
            float gf = __shfl_sync(m, act, 1, 4);
            float gg = __shfl_sync(m, act, 2, 4);
            float go = __shfl_sync(m, act, 3, 4);
            c = fmaf(gf, c, gi * gg);            // redundant in all 4 quad lanes
            float h = go * tanh_fast(c);
            if ((tid & 3) == 0) h_wr[u] = h;     // quad leader publishes h_t
        } else if (t > 0) {
            // aux warp: out[t-1] = fc_w . h_{t-1} + fc_b + x[t-1]
            const int l = tid - GATES;
            float p = fw0 * h_rd[l] + fw1 * h_rd[l + 32] + fw2 * h_rd[l + 64];
            #pragma unroll
            for (int off = 16; off > 0; off >>= 1)
                p += __shfl_xor_sync(0xffffffffu, p, off);
            if (l == 0)
                out[(size_t)(t - 1) * BATCH + b] = p + fcb + xs[t - 1];
        }

        __syncthreads();                 // single barrier: h_t published
        float* tmp = h_rd; h_rd = h_wr; h_wr = tmp;
    }

    // Final output: h_{T-1} sits in the read buffer after the last swap.
    if (tid >= GATES) {
        const int l = tid - GATES;
        float p = fw0 * h_rd[l] + fw1 * h_rd[l + 32] + fw2 * h_rd[l + 64];
        #pragma unroll
        for (int off = 16; off > 0; off >>= 1)
            p += __shfl_xor_sync(0xffffffffu, p, off);
        if (l == 0)
            out[(size_t)(TSTEPS - 1) * BATCH + b] = p + fcb + xs[TSTEPS - 1];
    }
}

extern "C" void kernel_launch(void* const* d_in, const int* in_sizes, int n_in,
                              void* d_out, int out_size)
{
    const float* x    = (const float*)d_in[0];
    const float* w_ih = (const float*)d_in[1];
    const float* w_hh = (const float*)d_in[2];
    const float* b_ih = (const float*)d_in[3];
    const float* b_hh = (const float*)d_in[4];
    const float* fc_w = (const float*)d_in[5];
    const float* fc_b = (const float*)d_in[6];
    float* out = (float*)d_out;

    cudaFuncSetAttribute(lstm_persist,
                         cudaFuncAttributeMaxDynamicSharedMemorySize,
                         (int)SMEM_BYTES);
    lstm_persist<<<BATCH, NTH, SMEM_BYTES>>>(x, w_ih, w_hh, b_ih, b_hh,
                                             fc_w, fc_b, out);
}